// round 15
// baseline (speedup 1.0000x reference)
#include <cuda_runtime.h>
#include <cstdint>

#define TPB 96
#define TILE 16
#define EPS_BN 1e-5f
#define RSTRIDE 40

// smem byte offsets (per CTA, ~36.5KB -> 4 CTAs/SM, reg-bound)
#define OFF_BIAS 0                 // 96 floats
#define OFF_T0   1024              // 7 groups * 2048B (16 rows x 128B fp32, SWZ)
#define OFF_T1   15360
#define OFF_R    29696             // 3 * 16 * RSTRIDE * 4 = 7680
#define SMEM_TOTAL 37376
#define DBUF (OFF_T1 - OFF_T0)

#define SWZ(o) ((o) ^ (((o) >> 3) & 0x70))

static __device__ __forceinline__ uint32_t smem_u32(const void* p) {
    uint32_t a;
    asm("{ .reg .u64 t; cvta.to.shared.u64 t, %1; cvt.u32.u64 %0, t; }" : "=r"(a) : "l"(p));
    return a;
}
static __device__ __forceinline__ uint32_t cvt_tf32(float x) {
    uint32_t r;
    asm("cvt.rna.tf32.f32 %0, %1;" : "=r"(r) : "f"(x));
    return r;
}
static __device__ __forceinline__ float4 lds128f(uint32_t a) {
    float4 v;
    asm volatile("ld.shared.v4.f32 {%0,%1,%2,%3}, [%4];"
                 : "=f"(v.x), "=f"(v.y), "=f"(v.z), "=f"(v.w) : "r"(a));
    return v;
}
static __device__ __forceinline__ void ldsm4(uint32_t* r, uint32_t addr) {
    asm volatile("ldmatrix.sync.aligned.m8n8.x4.shared.b16 {%0,%1,%2,%3}, [%4];"
                 : "=r"(r[0]), "=r"(r[1]), "=r"(r[2]), "=r"(r[3]) : "r"(addr));
}
static __device__ __forceinline__ void mma_tf32(float* d, uint32_t a0, uint32_t a1,
                                                uint32_t a2, uint32_t a3,
                                                uint32_t b0, uint32_t b1) {
    asm volatile("mma.sync.aligned.m16n8k8.row.col.f32.tf32.tf32.f32 "
                 "{%0,%1,%2,%3}, {%4,%5,%6,%7}, {%8,%9}, {%0,%1,%2,%3};"
                 : "+f"(d[0]), "+f"(d[1]), "+f"(d[2]), "+f"(d[3])
                 : "r"(a0), "r"(a1), "r"(a2), "r"(a3), "r"(b0), "r"(b1));
}
static __device__ __forceinline__ void cp16(uint32_t dst, const float4* src, uint32_t bytes) {
    const size_t g = __cvta_generic_to_global(src);
    asm volatile("cp.async.cg.shared.global [%0], [%1], 16, %2;"
                 :: "r"(dst), "l"(g), "r"(bytes) : "memory");
}
// 8 copies of one 128B row with a single base register + immediate offsets
static __device__ __forceinline__ void cp16x8(uint32_t d0, uint32_t d1, uint32_t d2,
                                              uint32_t d3, uint32_t d4, uint32_t d5,
                                              uint32_t d6, uint32_t d7,
                                              const float4* src, uint32_t bytes) {
    const size_t g = __cvta_generic_to_global(src);
    asm volatile(
        "cp.async.cg.shared.global [%0], [%8+0],   16, %9;\n\t"
        "cp.async.cg.shared.global [%1], [%8+16],  16, %9;\n\t"
        "cp.async.cg.shared.global [%2], [%8+32],  16, %9;\n\t"
        "cp.async.cg.shared.global [%3], [%8+48],  16, %9;\n\t"
        "cp.async.cg.shared.global [%4], [%8+64],  16, %9;\n\t"
        "cp.async.cg.shared.global [%5], [%8+80],  16, %9;\n\t"
        "cp.async.cg.shared.global [%6], [%8+96],  16, %9;\n\t"
        "cp.async.cg.shared.global [%7], [%8+112], 16, %9;\n\t"
        :: "r"(d0), "r"(d1), "r"(d2), "r"(d3), "r"(d4), "r"(d5), "r"(d6), "r"(d7),
           "l"(g), "r"(bytes) : "memory");
}
static __device__ __forceinline__ float sigmoid_fast(float v) {
    float th;
    asm("tanh.approx.f32 %0, %1;" : "=f"(th) : "f"(0.5f * v));
    return fmaf(th, 0.5f, 0.5f);
}

__global__ __launch_bounds__(TPB, 4) void recon_kernel(
    const float* __restrict__ f,
    const int*   __restrict__ nbr_prev,
    const int*   __restrict__ nbr_next,
    const float* __restrict__ W,
    const float* __restrict__ gamma,
    const float* __restrict__ beta,
    const float* __restrict__ mean,
    const float* __restrict__ var,
    float* __restrict__ out, int n)
{
    extern __shared__ char smem[];
    const uint32_t sb = smem_u32(smem);
    const int tid  = threadIdx.x;
    const int lane = tid & 31;
    const int br   = tid >> 5;       // branch 0..2 (one warp per branch)

    float* biasm = (float*)(smem + OFF_BIAS);

    if (tid < 96) {
        const float sc = gamma[tid] * rsqrtf(var[tid] + EPS_BN);
        biasm[tid] = beta[tid] - mean[tid] * sc;
    }
    __syncthreads();

    // ---- build this branch's B fragments directly from global W (BN folded) ----
    uint32_t breg[3][4][4][2];
    {
        float scj[4];
        #pragma unroll
        for (int nc = 0; nc < 4; nc++) {
            const int j = 8 * nc + (lane >> 2);
            scj[nc] = gamma[br * 32 + j] * rsqrtf(var[br * 32 + j] + EPS_BN);
        }
        #pragma unroll
        for (int t = 0; t < 3; t++) {
            const float* Wt = W + (br * 3 + t) * 1024;
            #pragma unroll
            for (int ks = 0; ks < 4; ks++) {
                const int i = ks * 8 + (lane & 3);
                #pragma unroll
                for (int nc = 0; nc < 4; nc++) {
                    const int j = 8 * nc + (lane >> 2);
                    breg[t][ks][nc][0] = cvt_tf32(__ldg(&Wt[i * 32 + j]) * scj[nc]);
                    breg[t][ks][nc][1] = cvt_tf32(__ldg(&Wt[(i + 4) * 32 + j]) * scj[nc]);
                }
            }
        }
    }

    const float4* __restrict__ f4 = (const float4*)f;
    const int ntiles = (n + TILE - 1) / TILE;
    const int grid = gridDim.x;

    // ---- per-thread staging geometry (constant across tiles) ----
    const int gst  = tid >> 4;               // neighbor group 0..5
    const int ast  = gst >> 1;               // axis
    const int rstn = tid & 15;               // neighbor row
    const int rc0 = tid >> 3, uc0 = tid & 7; // center part A (rows 0..11)
    const int s1  = tid + TPB;
    const bool c1v = (s1 < 128);             // center part B (threads 0..31)
    const int rc1 = s1 >> 3, uc1 = s1 & 7;
    const uint32_t dstc0 = OFF_T0 + SWZ((uint32_t)(rc0 * 128 + uc0 * 16));
    const uint32_t dstc1 = OFF_T0 + SWZ((uint32_t)(rc1 * 128 + uc1 * 16));
    uint32_t dstn[8];
    #pragma unroll
    for (int u = 0; u < 8; u++)
        dstn[u] = sb + OFF_T0 + (1 + gst) * 2048 + SWZ((uint32_t)(rstn * 128 + u * 16));
    // hoisted neighbor-index pointer: nptr[t*TILE] = nbr[ast*n + t*TILE + rstn]
    const int* __restrict__ nptr =
        ((gst & 1) ? nbr_next : nbr_prev) + (long)ast * n + rstn;

    // ---- MMA per-lane ldmatrix geometry ----
    const int mid   = lane >> 3;
    const int lrow  = (lane & 7) + ((mid & 1) << 3);
    const int c16   = (mid >> 1) << 4;
    const uint32_t xr = (uint32_t)((lrow & 7) * 16);
    const uint32_t rowoff = (uint32_t)(lrow * 128);
    uint32_t kso[4];
    #pragma unroll
    for (int ks = 0; ks < 4; ks++)
        kso[ks] = ((uint32_t)(ks * 32 + c16)) ^ xr;

    // ---- hoisted reduction-store addresses (rr=0; +1280 for rr=1) ----
    uint32_t rst[4];
    #pragma unroll
    for (int nc = 0; nc < 4; nc++)
        rst[nc] = sb + OFF_R +
            (uint32_t)((((br * 16 + (lane >> 2)) * RSTRIDE + 8 * nc + 2 * (lane & 3)) << 2));

    // ---- hoisted epilogue geometry ----
    const int row0 = tid >> 3, q0 = tid & 7;          // iter 0 (always valid)
    const int row1 = s1 >> 3,  q1 = s1 & 7;           // iter 1 (c1v only)
    const uint32_t rb0 = sb + OFF_R + (uint32_t)((row0 * RSTRIDE + 4 * q0) << 2);
    const uint32_t rb1 = sb + OFF_R + (uint32_t)((row1 * RSTRIDE + 4 * q1) << 2);
    const uint32_t xo0 = OFF_T0 + SWZ((uint32_t)(row0 * 128 + q0 * 16));
    const uint32_t xo1 = OFF_T0 + SWZ((uint32_t)(row1 * 128 + q1 * 16));
    float4* const outq0 = (float4*)out + (row0 * 8 + q0);
    float4* const outq1 = (float4*)out + (row1 * 8 + q1);

    // ---- prologue: stage tile0 into buf0; prefetch idx for tile1 ----
    int tile = blockIdx.x;
    {
        const int p = tile * TILE + rstn;
        int idx = -1;
        if (tile < ntiles && p < n) idx = __ldg(nptr + tile * TILE);
        if (tile < ntiles) {
            const int pbase = tile * TILE;
            { const int pc = pbase + rc0;
              cp16(sb + dstc0, &f4[(long)(pc < n ? pc : 0) * 8 + uc0], pc < n ? 16u : 0u); }
            if (c1v) { const int pc = pbase + rc1;
              cp16(sb + dstc1, &f4[(long)(pc < n ? pc : 0) * 8 + uc1], pc < n ? 16u : 0u); }
            cp16x8(dstn[0], dstn[1], dstn[2], dstn[3], dstn[4], dstn[5], dstn[6], dstn[7],
                   &f4[(long)(idx >= 0 ? idx : 0) * 8], (idx >= 0) ? 16u : 0u);
        }
        asm volatile("cp.async.commit_group;" ::: "memory");
    }
    int pidx1;
    {
        const int t1 = tile + grid;
        const int p = t1 * TILE + rstn;
        pidx1 = (t1 < ntiles && p < n) ? __ldg(nptr + t1 * TILE) : -1;
    }

    int cur = 0;
    for (; tile < ntiles; tile += grid) {
        asm volatile("cp.async.wait_group 0;" ::: "memory");
        __syncthreads();
        const uint32_t bufadd = cur ? (uint32_t)DBUF : 0u;
        const uint32_t tb = sb + OFF_T0 + bufadd;
        const int pbase = tile * TILE;
        const int ntile = tile + grid;

        // ---- stage tile t+1 NOW (latency covered by MMA+epilogue below) ----
        if (ntile < ntiles) {
            const uint32_t oadd = cur ? 0u : (uint32_t)DBUF;
            const int npb = ntile * TILE;
            { const int pc = npb + rc0;
              cp16(sb + dstc0 + oadd, &f4[(long)(pc < n ? pc : 0) * 8 + uc0], pc < n ? 16u : 0u); }
            if (c1v) { const int pc = npb + rc1;
              cp16(sb + dstc1 + oadd, &f4[(long)(pc < n ? pc : 0) * 8 + uc1], pc < n ? 16u : 0u); }
            cp16x8(dstn[0] + oadd, dstn[1] + oadd, dstn[2] + oadd, dstn[3] + oadd,
                   dstn[4] + oadd, dstn[5] + oadd, dstn[6] + oadd, dstn[7] + oadd,
                   &f4[(long)(pidx1 >= 0 ? pidx1 : 0) * 8], (pidx1 >= 0) ? 16u : 0u);
        }
        asm volatile("cp.async.commit_group;" ::: "memory");

        // ---- prefetch idx for tile t+2 (LDG covered by MMA) ----
        int pidx2 = -1;
        {
            const int t2 = ntile + grid;
            const int p = t2 * TILE + rstn;
            if (t2 < ntiles && p < n) pidx2 = __ldg(nptr + t2 * TILE);
        }

        // per-tap A bases with lane row folded in
        uint32_t gbs[3];
        gbs[0] = tb + (1 + 2 * br) * 2048 + rowoff;
        gbs[1] = tb + rowoff;
        gbs[2] = tb + (2 + 2 * br) * 2048 + rowoff;

        float acc[4][4];
        #pragma unroll
        for (int nc = 0; nc < 4; nc++) {
            const float2 b2 = *(const float2*)&biasm[br * 32 + 8 * nc + 2 * (lane & 3)];
            acc[nc][0] = acc[nc][2] = b2.x;
            acc[nc][1] = acc[nc][3] = b2.y;
        }

        // ---- software-pipelined 12-step MMA loop (ldmatrix.x4 A-frags) ----
        uint32_t af[2][4];
        ldsm4(af[0], gbs[0] + kso[0]);
        #pragma unroll
        for (int s = 0; s < 12; s++) {
            const int pb = s & 1;
            if (s < 11) {
                const int s1s = s + 1;
                ldsm4(af[pb ^ 1], gbs[s1s >> 2] + kso[s1s & 3]);
            }
            const int t = s >> 2, ks = s & 3;
            #pragma unroll
            for (int nc = 0; nc < 4; nc++)
                mma_tf32(acc[nc], af[pb][0], af[pb][1], af[pb][2], af[pb][3],
                         breg[t][ks][nc][0], breg[t][ks][nc][1]);
        }

        // ---- sigmoid + partial store (hoisted addresses) ----
        #pragma unroll
        for (int nc = 0; nc < 4; nc++) {
            asm volatile("st.shared.v2.f32 [%0], {%1, %2};"
                         :: "r"(rst[nc]), "f"(sigmoid_fast(acc[nc][0])),
                            "f"(sigmoid_fast(acc[nc][1])) : "memory");
            asm volatile("st.shared.v2.f32 [%0], {%1, %2};"
                         :: "r"(rst[nc] + 1280), "f"(sigmoid_fast(acc[nc][2])),
                            "f"(sigmoid_fast(acc[nc][3])) : "memory");
        }
        __syncthreads();

        // ---- epilogue: sum 3 branches, gate by exact fp32 x, store ----
        {
            const float4 s0 = lds128f(rb0);
            const float4 s1v = lds128f(rb0 + 16 * RSTRIDE * 4);
            const float4 s2 = lds128f(rb0 + 32 * RSTRIDE * 4);
            const float4 x  = lds128f(sb + bufadd + xo0);
            const int p = pbase + row0;
            if (p < n) {
                float4 v;
                v.x = (s0.x + s1v.x + s2.x) * x.x;
                v.y = (s0.y + s1v.y + s2.y) * x.y;
                v.z = (s0.z + s1v.z + s2.z) * x.z;
                v.w = (s0.w + s1v.w + s2.w) * x.w;
                outq0[pbase * 8] = v;
            }
        }
        if (c1v) {
            const float4 s0 = lds128f(rb1);
            const float4 s1v = lds128f(rb1 + 16 * RSTRIDE * 4);
            const float4 s2 = lds128f(rb1 + 32 * RSTRIDE * 4);
            const float4 x  = lds128f(sb + bufadd + xo1);
            const int p = pbase + row1;
            if (p < n) {
                float4 v;
                v.x = (s0.x + s1v.x + s2.x) * x.x;
                v.y = (s0.y + s1v.y + s2.y) * x.y;
                v.z = (s0.z + s1v.z + s2.z) * x.z;
                v.w = (s0.w + s1v.w + s2.w) * x.w;
                outq1[pbase * 8] = v;
            }
        }
        pidx1 = pidx2;
        cur ^= 1;
    }
}

extern "C" void kernel_launch(void* const* d_in, const int* in_sizes, int n_in,
                              void* d_out, int out_size) {
    const float* f     = (const float*)d_in[0];
    const int*   nprev = (const int*)  d_in[1];
    const int*   nnext = (const int*)  d_in[2];
    const float* W     = (const float*)d_in[3];
    const float* gamma = (const float*)d_in[4];
    const float* beta  = (const float*)d_in[5];
    const float* mean  = (const float*)d_in[6];
    const float* var   = (const float*)d_in[7];
    const int n = in_sizes[0] / 32;

    cudaFuncSetAttribute(recon_kernel, cudaFuncAttributeMaxDynamicSharedMemorySize,
                         SMEM_TOTAL);
    recon_kernel<<<592, TPB, SMEM_TOTAL>>>(f, nprev, nnext, W, gamma, beta, mean, var,
                                           (float*)d_out, n);
}

// round 16
// speedup vs baseline: 1.3549x; 1.3549x over previous
#include <cuda_runtime.h>
#include <cstdint>

#define TPB 128
#define TILE 16
#define EPS_BN 1e-5f
#define RSTRIDE 40

// smem byte offsets (per CTA, ~36.5KB -> 3 CTAs/SM, reg-bound)
#define OFF_BIAS 0                 // 96 floats
#define OFF_T0   1024              // 7 groups * 2048B (16 rows x 128B fp32, SWZ)
#define OFF_T1   15360
#define OFF_R    29696             // 3 * 16 * RSTRIDE * 4 = 7680
#define SMEM_TOTAL 37376
#define DBUF (OFF_T1 - OFF_T0)

#define SWZ(o) ((o) ^ (((o) >> 3) & 0x70))

static __device__ __forceinline__ uint32_t smem_u32(const void* p) {
    uint32_t a;
    asm("{ .reg .u64 t; cvta.to.shared.u64 t, %1; cvt.u32.u64 %0, t; }" : "=r"(a) : "l"(p));
    return a;
}
static __device__ __forceinline__ uint32_t cvt_tf32(float x) {
    uint32_t r;
    asm("cvt.rna.tf32.f32 %0, %1;" : "=r"(r) : "f"(x));
    return r;
}
static __device__ __forceinline__ float4 lds128f(uint32_t a) {
    float4 v;
    asm volatile("ld.shared.v4.f32 {%0,%1,%2,%3}, [%4];"
                 : "=f"(v.x), "=f"(v.y), "=f"(v.z), "=f"(v.w) : "r"(a));
    return v;
}
static __device__ __forceinline__ void ldsm4(uint32_t* r, uint32_t addr) {
    asm volatile("ldmatrix.sync.aligned.m8n8.x4.shared.b16 {%0,%1,%2,%3}, [%4];"
                 : "=r"(r[0]), "=r"(r[1]), "=r"(r[2]), "=r"(r[3]) : "r"(addr));
}
static __device__ __forceinline__ void mma_tf32(float* d, uint32_t a0, uint32_t a1,
                                                uint32_t a2, uint32_t a3,
                                                uint32_t b0, uint32_t b1) {
    asm volatile("mma.sync.aligned.m16n8k8.row.col.f32.tf32.tf32.f32 "
                 "{%0,%1,%2,%3}, {%4,%5,%6,%7}, {%8,%9}, {%0,%1,%2,%3};"
                 : "+f"(d[0]), "+f"(d[1]), "+f"(d[2]), "+f"(d[3])
                 : "r"(a0), "r"(a1), "r"(a2), "r"(a3), "r"(b0), "r"(b1));
}
// 4 copies (center half-row) with src immediates
static __device__ __forceinline__ void cp16x4(uint32_t d0, uint32_t d1, uint32_t d2,
                                              uint32_t d3, const float4* src,
                                              uint32_t bytes) {
    const size_t g = __cvta_generic_to_global(src);
    asm volatile(
        "cp.async.cg.shared.global [%0], [%4+0],  16, %5;\n\t"
        "cp.async.cg.shared.global [%1], [%4+16], 16, %5;\n\t"
        "cp.async.cg.shared.global [%2], [%4+32], 16, %5;\n\t"
        "cp.async.cg.shared.global [%3], [%4+48], 16, %5;\n\t"
        :: "r"(d0), "r"(d1), "r"(d2), "r"(d3), "l"(g), "r"(bytes) : "memory");
}
// 8 copies of one 128B row with a single base register + immediate offsets
static __device__ __forceinline__ void cp16x8(uint32_t d0, uint32_t d1, uint32_t d2,
                                              uint32_t d3, uint32_t d4, uint32_t d5,
                                              uint32_t d6, uint32_t d7,
                                              const float4* src, uint32_t bytes) {
    const size_t g = __cvta_generic_to_global(src);
    asm volatile(
        "cp.async.cg.shared.global [%0], [%8+0],   16, %9;\n\t"
        "cp.async.cg.shared.global [%1], [%8+16],  16, %9;\n\t"
        "cp.async.cg.shared.global [%2], [%8+32],  16, %9;\n\t"
        "cp.async.cg.shared.global [%3], [%8+48],  16, %9;\n\t"
        "cp.async.cg.shared.global [%4], [%8+64],  16, %9;\n\t"
        "cp.async.cg.shared.global [%5], [%8+80],  16, %9;\n\t"
        "cp.async.cg.shared.global [%6], [%8+96],  16, %9;\n\t"
        "cp.async.cg.shared.global [%7], [%8+112], 16, %9;\n\t"
        :: "r"(d0), "r"(d1), "r"(d2), "r"(d3), "r"(d4), "r"(d5), "r"(d6), "r"(d7),
           "l"(g), "r"(bytes) : "memory");
}
static __device__ __forceinline__ float sigmoid_fast(float v) {
    float th;
    asm("tanh.approx.f32 %0, %1;" : "=f"(th) : "f"(0.5f * v));
    return fmaf(th, 0.5f, 0.5f);
}

__global__ __launch_bounds__(TPB, 3) void recon_kernel(
    const float* __restrict__ f,
    const int*   __restrict__ nbr_prev,
    const int*   __restrict__ nbr_next,
    const float* __restrict__ W,
    const float* __restrict__ gamma,
    const float* __restrict__ beta,
    const float* __restrict__ mean,
    const float* __restrict__ var,
    float* __restrict__ out, int n)
{
    extern __shared__ char smem[];
    const uint32_t sb = smem_u32(smem);
    const int tid  = threadIdx.x;
    const int lane = tid & 31;
    const int br   = tid >> 5;       // 0..2 MMA branch warps; 3 = staging warp

    float* biasm = (float*)(smem + OFF_BIAS);

    if (tid < 96) {
        const float sc = gamma[tid] * rsqrtf(var[tid] + EPS_BN);
        biasm[tid] = beta[tid] - mean[tid] * sc;
    }
    __syncthreads();

    // ---- MMA warps: build this branch's B fragments from global W (BN folded) ----
    uint32_t breg[3][4][4][2];
    if (br < 3) {
        float scj[4];
        #pragma unroll
        for (int nc = 0; nc < 4; nc++) {
            const int j = 8 * nc + (lane >> 2);
            scj[nc] = gamma[br * 32 + j] * rsqrtf(var[br * 32 + j] + EPS_BN);
        }
        #pragma unroll
        for (int t = 0; t < 3; t++) {
            const float* Wt = W + (br * 3 + t) * 1024;
            #pragma unroll
            for (int ks = 0; ks < 4; ks++) {
                const int i = ks * 8 + (lane & 3);
                #pragma unroll
                for (int nc = 0; nc < 4; nc++) {
                    const int j = 8 * nc + (lane >> 2);
                    breg[t][ks][nc][0] = cvt_tf32(__ldg(&Wt[i * 32 + j]) * scj[nc]);
                    breg[t][ks][nc][1] = cvt_tf32(__ldg(&Wt[(i + 4) * 32 + j]) * scj[nc]);
                }
            }
        }
    }

    const float4* __restrict__ f4 = (const float4*)f;
    const int ntiles = (n + TILE - 1) / TILE;
    const int grid = gridDim.x;

    // ---- warp-3 staging geometry (s = tid-96, 0..31) ----
    const int s = tid & 31;                    // == tid-96 on warp 3
    const int rcC = s >> 1;                    // center row
    const int hC  = (s & 1) * 4;               // center u-quad base
    uint32_t dstc[4];
    #pragma unroll
    for (int j = 0; j < 4; j++)
        dstc[j] = sb + OFF_T0 + SWZ((uint32_t)(rcC * 128 + (hC + j) * 16));
    int rN[3];
    const int* nptrk[3];
    uint32_t dstn3[3][8];
    #pragma unroll
    for (int k = 0; k < 3; k++) {
        const int flat = s + 32 * k;           // 0..95
        const int g = flat >> 4, rr = flat & 15;
        rN[k] = rr;
        nptrk[k] = ((g & 1) ? nbr_next : nbr_prev) + (long)(g >> 1) * n + rr;
        #pragma unroll
        for (int u = 0; u < 8; u++)
            dstn3[k][u] = sb + OFF_T0 + (1 + g) * 2048 + SWZ((uint32_t)(rr * 128 + u * 16));
    }

    // ---- MMA per-lane ldmatrix geometry ----
    const int mid   = lane >> 3;
    const int lrow  = (lane & 7) + ((mid & 1) << 3);
    const int c16   = (mid >> 1) << 4;
    const uint32_t xr = (uint32_t)((lrow & 7) * 16);
    const uint32_t rowoff = (uint32_t)(lrow * 128);
    uint32_t kso[4];
    #pragma unroll
    for (int ks = 0; ks < 4; ks++)
        kso[ks] = ((uint32_t)(ks * 32 + c16)) ^ xr;

    // ---- MMA warps: hoisted reduction-store addresses ----
    uint32_t rst[4];
    #pragma unroll
    for (int nc = 0; nc < 4; nc++)
        rst[nc] = sb + OFF_R +
            (uint32_t)((((br * 16 + (lane >> 2)) * RSTRIDE + 8 * nc + 2 * (lane & 3)) << 2));

    // ---- epilogue geometry: 1 unit per thread (128 units) ----
    const int erow = tid >> 3, eq = tid & 7;
    const uint32_t rbE = sb + OFF_R + (uint32_t)((erow * RSTRIDE + 4 * eq) << 2);
    const uint32_t xoE = OFF_T0 + SWZ((uint32_t)(erow * 128 + eq * 16));
    float4* const outE = (float4*)out + (erow * 8 + eq);

    // ---- prologue (warp 3): stage tile0 into buf0; prefetch idx for tile1 ----
    int tile = blockIdx.x;
    int pidx1[3] = {-1, -1, -1};
    if (br == 3) {
        if (tile < ntiles) {
            const int pbase = tile * TILE;
            int idx0[3];
            #pragma unroll
            for (int k = 0; k < 3; k++) {
                const int p = pbase + rN[k];
                idx0[k] = (p < n) ? __ldg(nptrk[k] + pbase) : -1;
            }
            const int pc = pbase + rcC;
            cp16x4(dstc[0], dstc[1], dstc[2], dstc[3],
                   &f4[(long)(pc < n ? pc : 0) * 8 + hC], (pc < n) ? 16u : 0u);
            #pragma unroll
            for (int k = 0; k < 3; k++)
                cp16x8(dstn3[k][0], dstn3[k][1], dstn3[k][2], dstn3[k][3],
                       dstn3[k][4], dstn3[k][5], dstn3[k][6], dstn3[k][7],
                       &f4[(long)(idx0[k] >= 0 ? idx0[k] : 0) * 8],
                       (idx0[k] >= 0) ? 16u : 0u);
        }
        asm volatile("cp.async.commit_group;" ::: "memory");
        const int t1 = tile + grid;
        #pragma unroll
        for (int k = 0; k < 3; k++) {
            const int p = t1 * TILE + rN[k];
            pidx1[k] = (t1 < ntiles && p < n) ? __ldg(nptrk[k] + t1 * TILE) : -1;
        }
    }

    int cur = 0;
    for (; tile < ntiles; tile += grid) {
        asm volatile("cp.async.wait_group 0;" ::: "memory");
        __syncthreads();
        const uint32_t bufadd = cur ? (uint32_t)DBUF : 0u;
        const int pbase = tile * TILE;
        const int ntile = tile + grid;

        if (br == 3) {
            // ---- warp 3: stage tile t+1 + prefetch idx t+2 ----
            if (ntile < ntiles) {
                const uint32_t oadd = cur ? 0u : (uint32_t)DBUF;
                const int npb = ntile * TILE;
                const int pc = npb + rcC;
                cp16x4(dstc[0] + oadd, dstc[1] + oadd, dstc[2] + oadd, dstc[3] + oadd,
                       &f4[(long)(pc < n ? pc : 0) * 8 + hC], (pc < n) ? 16u : 0u);
                #pragma unroll
                for (int k = 0; k < 3; k++)
                    cp16x8(dstn3[k][0] + oadd, dstn3[k][1] + oadd, dstn3[k][2] + oadd,
                           dstn3[k][3] + oadd, dstn3[k][4] + oadd, dstn3[k][5] + oadd,
                           dstn3[k][6] + oadd, dstn3[k][7] + oadd,
                           &f4[(long)(pidx1[k] >= 0 ? pidx1[k] : 0) * 8],
                           (pidx1[k] >= 0) ? 16u : 0u);
            }
            asm volatile("cp.async.commit_group;" ::: "memory");
            const int t2 = ntile + grid;
            #pragma unroll
            for (int k = 0; k < 3; k++) {
                const int p = t2 * TILE + rN[k];
                pidx1[k] = (t2 < ntiles && p < n) ? __ldg(nptrk[k] + t2 * TILE) : -1;
            }
        } else {
            // ---- MMA warps: 12-step pipelined MMA + sigmoid + reduction store ----
            const uint32_t tb = sb + OFF_T0 + bufadd;
            uint32_t gbs[3];
            gbs[0] = tb + (1 + 2 * br) * 2048 + rowoff;
            gbs[1] = tb + rowoff;
            gbs[2] = tb + (2 + 2 * br) * 2048 + rowoff;

            float acc[4][4];
            #pragma unroll
            for (int nc = 0; nc < 4; nc++) {
                const float2 b2 = *(const float2*)&biasm[br * 32 + 8 * nc + 2 * (lane & 3)];
                acc[nc][0] = acc[nc][2] = b2.x;
                acc[nc][1] = acc[nc][3] = b2.y;
            }

            uint32_t af[2][4];
            ldsm4(af[0], gbs[0] + kso[0]);
            #pragma unroll
            for (int st = 0; st < 12; st++) {
                const int pb = st & 1;
                if (st < 11) {
                    const int s1s = st + 1;
                    ldsm4(af[pb ^ 1], gbs[s1s >> 2] + kso[s1s & 3]);
                }
                const int t = st >> 2, ks = st & 3;
                #pragma unroll
                for (int nc = 0; nc < 4; nc++)
                    mma_tf32(acc[nc], af[pb][0], af[pb][1], af[pb][2], af[pb][3],
                             breg[t][ks][nc][0], breg[t][ks][nc][1]);
            }

            #pragma unroll
            for (int nc = 0; nc < 4; nc++) {
                asm volatile("st.shared.v2.f32 [%0], {%1, %2};"
                             :: "r"(rst[nc]), "f"(sigmoid_fast(acc[nc][0])),
                                "f"(sigmoid_fast(acc[nc][1])) : "memory");
                asm volatile("st.shared.v2.f32 [%0], {%1, %2};"
                             :: "r"(rst[nc] + 1280), "f"(sigmoid_fast(acc[nc][2])),
                                "f"(sigmoid_fast(acc[nc][3])) : "memory");
            }
        }
        __syncthreads();

        // ---- epilogue: all 128 threads, one (row,q) unit each ----
        {
            const float4 s0  = lds128f(rbE);
            const float4 s1v = lds128f(rbE + 16 * RSTRIDE * 4);
            const float4 s2  = lds128f(rbE + 32 * RSTRIDE * 4);
            const float4 x   = lds128f(sb + bufadd + xoE);
            const int p = pbase + erow;
            if (p < n) {
                float4 v;
                v.x = (s0.x + s1v.x + s2.x) * x.x;
                v.y = (s0.y + s1v.y + s2.y) * x.y;
                v.z = (s0.z + s1v.z + s2.z) * x.z;
                v.w = (s0.w + s1v.w + s2.w) * x.w;
                outE[pbase * 8] = v;
            }
        }
        cur ^= 1;
    }
}

extern "C" void kernel_launch(void* const* d_in, const int* in_sizes, int n_in,
                              void* d_out, int out_size) {
    const float* f     = (const float*)d_in[0];
    const int*   nprev = (const int*)  d_in[1];
    const int*   nnext = (const int*)  d_in[2];
    const float* W     = (const float*)d_in[3];
    const float* gamma = (const float*)d_in[4];
    const float* beta  = (const float*)d_in[5];
    const float* mean  = (const float*)d_in[6];
    const float* var   = (const float*)d_in[7];
    const int n = in_sizes[0] / 32;

    cudaFuncSetAttribute(recon_kernel, cudaFuncAttributeMaxDynamicSharedMemorySize,
                         SMEM_TOTAL);
    recon_kernel<<<444, TPB, SMEM_TOTAL>>>(f, nprev, nnext, W, gamma, beta, mean, var,
                                           (float*)d_out, n);
}

// round 17
// speedup vs baseline: 1.5345x; 1.1325x over previous
#include <cuda_runtime.h>
#include <cstdint>

#define TPB 96
#define TILE 16
#define EPS_BN 1e-5f
#define RSTRIDE 40

// smem byte offsets (per CTA, 51712B -> 4 CTAs/SM, reg-bound)
#define OFF_BIAS 0                 // 96 floats
#define OFF_B0   1024              // 3 tile buffers, each 7 groups * 2048B = 14336B
#define OFF_B1   15360
#define OFF_B2   29696
#define OFF_R    44032             // 3 * 16 * RSTRIDE * 4 = 7680
#define SMEM_TOTAL 51712

#define SWZ(o) ((o) ^ (((o) >> 3) & 0x70))

static __device__ __forceinline__ uint32_t smem_u32(const void* p) {
    uint32_t a;
    asm("{ .reg .u64 t; cvta.to.shared.u64 t, %1; cvt.u32.u64 %0, t; }" : "=r"(a) : "l"(p));
    return a;
}
static __device__ __forceinline__ uint32_t cvt_tf32(float x) {
    uint32_t r;
    asm("cvt.rna.tf32.f32 %0, %1;" : "=r"(r) : "f"(x));
    return r;
}
static __device__ __forceinline__ float4 lds128f(uint32_t a) {
    float4 v;
    asm volatile("ld.shared.v4.f32 {%0,%1,%2,%3}, [%4];"
                 : "=f"(v.x), "=f"(v.y), "=f"(v.z), "=f"(v.w) : "r"(a));
    return v;
}
static __device__ __forceinline__ void ldsm4(uint32_t* r, uint32_t addr) {
    asm volatile("ldmatrix.sync.aligned.m8n8.x4.shared.b16 {%0,%1,%2,%3}, [%4];"
                 : "=r"(r[0]), "=r"(r[1]), "=r"(r[2]), "=r"(r[3]) : "r"(addr));
}
static __device__ __forceinline__ void mma_tf32(float* d, uint32_t a0, uint32_t a1,
                                                uint32_t a2, uint32_t a3,
                                                uint32_t b0, uint32_t b1) {
    asm volatile("mma.sync.aligned.m16n8k8.row.col.f32.tf32.tf32.f32 "
                 "{%0,%1,%2,%3}, {%4,%5,%6,%7}, {%8,%9}, {%0,%1,%2,%3};"
                 : "+f"(d[0]), "+f"(d[1]), "+f"(d[2]), "+f"(d[3])
                 : "r"(a0), "r"(a1), "r"(a2), "r"(a3), "r"(b0), "r"(b1));
}
static __device__ __forceinline__ void cp16(uint32_t dst, const float4* src, uint32_t bytes) {
    const size_t g = __cvta_generic_to_global(src);
    asm volatile("cp.async.cg.shared.global [%0], [%1], 16, %2;"
                 :: "r"(dst), "l"(g), "r"(bytes) : "memory");
}
// 8 copies of one 128B row with a single base register + immediate offsets
static __device__ __forceinline__ void cp16x8(uint32_t d0, uint32_t d1, uint32_t d2,
                                              uint32_t d3, uint32_t d4, uint32_t d5,
                                              uint32_t d6, uint32_t d7,
                                              const float4* src, uint32_t bytes) {
    const size_t g = __cvta_generic_to_global(src);
    asm volatile(
        "cp.async.cg.shared.global [%0], [%8+0],   16, %9;\n\t"
        "cp.async.cg.shared.global [%1], [%8+16],  16, %9;\n\t"
        "cp.async.cg.shared.global [%2], [%8+32],  16, %9;\n\t"
        "cp.async.cg.shared.global [%3], [%8+48],  16, %9;\n\t"
        "cp.async.cg.shared.global [%4], [%8+64],  16, %9;\n\t"
        "cp.async.cg.shared.global [%5], [%8+80],  16, %9;\n\t"
        "cp.async.cg.shared.global [%6], [%8+96],  16, %9;\n\t"
        "cp.async.cg.shared.global [%7], [%8+112], 16, %9;\n\t"
        :: "r"(d0), "r"(d1), "r"(d2), "r"(d3), "r"(d4), "r"(d5), "r"(d6), "r"(d7),
           "l"(g), "r"(bytes) : "memory");
}
static __device__ __forceinline__ float sigmoid_fast(float v) {
    float th;
    asm("tanh.approx.f32 %0, %1;" : "=f"(th) : "f"(0.5f * v));
    return fmaf(th, 0.5f, 0.5f);
}

__global__ __launch_bounds__(TPB, 4) void recon_kernel(
    const float* __restrict__ f,
    const int*   __restrict__ nbr_prev,
    const int*   __restrict__ nbr_next,
    const float* __restrict__ W,
    const float* __restrict__ gamma,
    const float* __restrict__ beta,
    const float* __restrict__ mean,
    const float* __restrict__ var,
    float* __restrict__ out, int n)
{
    extern __shared__ char smem[];
    const uint32_t sb = smem_u32(smem);
    const int tid  = threadIdx.x;
    const int lane = tid & 31;
    const int br   = tid >> 5;       // branch 0..2 (one warp per branch)

    float* biasm = (float*)(smem + OFF_BIAS);

    if (tid < 96) {
        const float sc = gamma[tid] * rsqrtf(var[tid] + EPS_BN);
        biasm[tid] = beta[tid] - mean[tid] * sc;
    }
    __syncthreads();

    // ---- build this branch's B fragments directly from global W (BN folded) ----
    uint32_t breg[3][4][4][2];
    {
        float scj[4];
        #pragma unroll
        for (int nc = 0; nc < 4; nc++) {
            const int j = 8 * nc + (lane >> 2);
            scj[nc] = gamma[br * 32 + j] * rsqrtf(var[br * 32 + j] + EPS_BN);
        }
        #pragma unroll
        for (int t = 0; t < 3; t++) {
            const float* Wt = W + (br * 3 + t) * 1024;
            #pragma unroll
            for (int ks = 0; ks < 4; ks++) {
                const int i = ks * 8 + (lane & 3);
                #pragma unroll
                for (int nc = 0; nc < 4; nc++) {
                    const int j = 8 * nc + (lane >> 2);
                    breg[t][ks][nc][0] = cvt_tf32(__ldg(&Wt[i * 32 + j]) * scj[nc]);
                    breg[t][ks][nc][1] = cvt_tf32(__ldg(&Wt[(i + 4) * 32 + j]) * scj[nc]);
                }
            }
        }
    }

    const float4* __restrict__ f4 = (const float4*)f;
    const int ntiles = (n + TILE - 1) / TILE;
    const int grid = gridDim.x;

    // ---- per-thread staging geometry (relative to a tile-buffer base) ----
    const int gst  = tid >> 4;               // neighbor group 0..5
    const int ast  = gst >> 1;               // axis
    const int rstn = tid & 15;               // neighbor row
    const int rc0 = tid >> 3, uc0 = tid & 7; // center part A (rows 0..11)
    const int s1  = tid + TPB;
    const bool c1v = (s1 < 128);             // center part B (threads 0..31)
    const int rc1 = s1 >> 3, uc1 = s1 & 7;
    const uint32_t dstc0 = SWZ((uint32_t)(rc0 * 128 + uc0 * 16));
    const uint32_t dstc1 = SWZ((uint32_t)(rc1 * 128 + uc1 * 16));
    uint32_t dstn[8];
    #pragma unroll
    for (int u = 0; u < 8; u++)
        dstn[u] = (uint32_t)((1 + gst) * 2048) + SWZ((uint32_t)(rstn * 128 + u * 16));
    const int* __restrict__ nptr =
        ((gst & 1) ? nbr_next : nbr_prev) + (long)ast * n + rstn;

    // ---- MMA per-lane ldmatrix geometry ----
    const int mid   = lane >> 3;
    const int lrow  = (lane & 7) + ((mid & 1) << 3);
    const int c16   = (mid >> 1) << 4;
    const uint32_t xr = (uint32_t)((lrow & 7) * 16);
    const uint32_t rowoff = (uint32_t)(lrow * 128);
    uint32_t kso[4];
    #pragma unroll
    for (int ks = 0; ks < 4; ks++)
        kso[ks] = ((uint32_t)(ks * 32 + c16)) ^ xr;

    // ---- hoisted reduction-store addresses (rr=0; +1280 for rr=1) ----
    uint32_t rst[4];
    #pragma unroll
    for (int nc = 0; nc < 4; nc++)
        rst[nc] = sb + OFF_R +
            (uint32_t)((((br * 16 + (lane >> 2)) * RSTRIDE + 8 * nc + 2 * (lane & 3)) << 2));

    // ---- hoisted epilogue geometry ----
    const int row0 = tid >> 3, q0 = tid & 7;
    const int row1 = s1 >> 3,  q1 = s1 & 7;
    const uint32_t rb0 = sb + OFF_R + (uint32_t)((row0 * RSTRIDE + 4 * q0) << 2);
    const uint32_t rb1 = sb + OFF_R + (uint32_t)((row1 * RSTRIDE + 4 * q1) << 2);
    const uint32_t xo0 = SWZ((uint32_t)(row0 * 128 + q0 * 16));
    const uint32_t xo1 = SWZ((uint32_t)(row1 * 128 + q1 * 16));
    float4* const outq0 = (float4*)out + (row0 * 8 + q0);
    float4* const outq1 = (float4*)out + (row1 * 8 + q1);

    // ---- tri-buffer rotation registers ----
    uint32_t tbcur  = sb + OFF_B0;   // buffer of current tile
    uint32_t tbnext = sb + OFF_B1;   // buffer of tile t+1
    uint32_t tbprev = sb + OFF_B2;   // stage target (== buffer (t+2)%3)

    int tile = blockIdx.x;

    // ---- prologue: stage tile0 -> B0, tile1 -> B1; prefetch idx for tile2 ----
    {
        const int p = tile * TILE + rstn;
        const int idx = (tile < ntiles && p < n) ? __ldg(nptr + tile * TILE) : -1;
        if (tile < ntiles) {
            const int pbase = tile * TILE;
            { const int pc = pbase + rc0;
              cp16(tbcur + dstc0, &f4[(long)(pc < n ? pc : 0) * 8 + uc0], pc < n ? 16u : 0u); }
            if (c1v) { const int pc = pbase + rc1;
              cp16(tbcur + dstc1, &f4[(long)(pc < n ? pc : 0) * 8 + uc1], pc < n ? 16u : 0u); }
            cp16x8(tbcur + dstn[0], tbcur + dstn[1], tbcur + dstn[2], tbcur + dstn[3],
                   tbcur + dstn[4], tbcur + dstn[5], tbcur + dstn[6], tbcur + dstn[7],
                   &f4[(long)(idx >= 0 ? idx : 0) * 8], (idx >= 0) ? 16u : 0u);
        }
        asm volatile("cp.async.commit_group;" ::: "memory");
    }
    {
        const int t1 = tile + grid;
        const int p = t1 * TILE + rstn;
        const int idx = (t1 < ntiles && p < n) ? __ldg(nptr + t1 * TILE) : -1;
        if (t1 < ntiles) {
            const int pbase = t1 * TILE;
            { const int pc = pbase + rc0;
              cp16(tbnext + dstc0, &f4[(long)(pc < n ? pc : 0) * 8 + uc0], pc < n ? 16u : 0u); }
            if (c1v) { const int pc = pbase + rc1;
              cp16(tbnext + dstc1, &f4[(long)(pc < n ? pc : 0) * 8 + uc1], pc < n ? 16u : 0u); }
            cp16x8(tbnext + dstn[0], tbnext + dstn[1], tbnext + dstn[2], tbnext + dstn[3],
                   tbnext + dstn[4], tbnext + dstn[5], tbnext + dstn[6], tbnext + dstn[7],
                   &f4[(long)(idx >= 0 ? idx : 0) * 8], (idx >= 0) ? 16u : 0u);
        }
        asm volatile("cp.async.commit_group;" ::: "memory");
    }
    int pidxS;   // idx for the next tile to stage (tile+2*grid)
    {
        const int t2 = tile + 2 * grid;
        const int p = t2 * TILE + rstn;
        pidxS = (t2 < ntiles && p < n) ? __ldg(nptr + t2 * TILE) : -1;
    }

    for (; tile < ntiles; tile += grid) {
        // wait for current tile's group (newest group may stay in flight)
        asm volatile("cp.async.wait_group 1;" ::: "memory");
        __syncthreads();
        const uint32_t tb = tbcur;
        const int pbase = tile * TILE;

        // ---- stage tile t+2 into tbprev (freed by the barrier above) ----
        {
            const int stile = tile + 2 * grid;
            if (stile < ntiles) {
                const int npb = stile * TILE;
                { const int pc = npb + rc0;
                  cp16(tbprev + dstc0, &f4[(long)(pc < n ? pc : 0) * 8 + uc0], pc < n ? 16u : 0u); }
                if (c1v) { const int pc = npb + rc1;
                  cp16(tbprev + dstc1, &f4[(long)(pc < n ? pc : 0) * 8 + uc1], pc < n ? 16u : 0u); }
                cp16x8(tbprev + dstn[0], tbprev + dstn[1], tbprev + dstn[2], tbprev + dstn[3],
                       tbprev + dstn[4], tbprev + dstn[5], tbprev + dstn[6], tbprev + dstn[7],
                       &f4[(long)(pidxS >= 0 ? pidxS : 0) * 8], (pidxS >= 0) ? 16u : 0u);
            }
            asm volatile("cp.async.commit_group;" ::: "memory");
        }
        // ---- prefetch idx for tile t+3 (LDG covered by MMA) ----
        {
            const int t3 = tile + 3 * grid;
            const int p = t3 * TILE + rstn;
            pidxS = (t3 < ntiles && p < n) ? __ldg(nptr + t3 * TILE) : -1;
        }

        // per-tap A bases with lane row folded in
        uint32_t gbs[3];
        gbs[0] = tb + (1 + 2 * br) * 2048 + rowoff;
        gbs[1] = tb + rowoff;
        gbs[2] = tb + (2 + 2 * br) * 2048 + rowoff;

        float acc[4][4];
        #pragma unroll
        for (int nc = 0; nc < 4; nc++) {
            const float2 b2 = *(const float2*)&biasm[br * 32 + 8 * nc + 2 * (lane & 3)];
            acc[nc][0] = acc[nc][2] = b2.x;
            acc[nc][1] = acc[nc][3] = b2.y;
        }

        // ---- software-pipelined 12-step MMA loop (ldmatrix.x4 A-frags) ----
        uint32_t af[2][4];
        ldsm4(af[0], gbs[0] + kso[0]);
        #pragma unroll
        for (int s = 0; s < 12; s++) {
            const int pb = s & 1;
            if (s < 11) {
                const int s1s = s + 1;
                ldsm4(af[pb ^ 1], gbs[s1s >> 2] + kso[s1s & 3]);
            }
            const int t = s >> 2, ks = s & 3;
            #pragma unroll
            for (int nc = 0; nc < 4; nc++)
                mma_tf32(acc[nc], af[pb][0], af[pb][1], af[pb][2], af[pb][3],
                         breg[t][ks][nc][0], breg[t][ks][nc][1]);
        }

        // ---- sigmoid + partial store (hoisted addresses) ----
        #pragma unroll
        for (int nc = 0; nc < 4; nc++) {
            asm volatile("st.shared.v2.f32 [%0], {%1, %2};"
                         :: "r"(rst[nc]), "f"(sigmoid_fast(acc[nc][0])),
                            "f"(sigmoid_fast(acc[nc][1])) : "memory");
            asm volatile("st.shared.v2.f32 [%0], {%1, %2};"
                         :: "r"(rst[nc] + 1280), "f"(sigmoid_fast(acc[nc][2])),
                            "f"(sigmoid_fast(acc[nc][3])) : "memory");
        }
        __syncthreads();

        // ---- epilogue: sum 3 branches, gate by exact fp32 x, store ----
        {
            const float4 s0 = lds128f(rb0);
            const float4 s1v = lds128f(rb0 + 16 * RSTRIDE * 4);
            const float4 s2 = lds128f(rb0 + 32 * RSTRIDE * 4);
            const float4 x  = lds128f(tb + xo0);
            const int p = pbase + row0;
            if (p < n) {
                float4 v;
                v.x = (s0.x + s1v.x + s2.x) * x.x;
                v.y = (s0.y + s1v.y + s2.y) * x.y;
                v.z = (s0.z + s1v.z + s2.z) * x.z;
                v.w = (s0.w + s1v.w + s2.w) * x.w;
                outq0[pbase * 8] = v;
            }
        }
        if (c1v) {
            const float4 s0 = lds128f(rb1);
            const float4 s1v = lds128f(rb1 + 16 * RSTRIDE * 4);
            const float4 s2 = lds128f(rb1 + 32 * RSTRIDE * 4);
            const float4 x  = lds128f(tb + xo1);
            const int p = pbase + row1;
            if (p < n) {
                float4 v;
                v.x = (s0.x + s1v.x + s2.x) * x.x;
                v.y = (s0.y + s1v.y + s2.y) * x.y;
                v.z = (s0.z + s1v.z + s2.z) * x.z;
                v.w = (s0.w + s1v.w + s2.w) * x.w;
                outq1[pbase * 8] = v;
            }
        }
        // rotate buffers: (prev, cur, next) <- (cur, next, prev)
        const uint32_t t0 = tbprev;
        tbprev = tbcur;
        tbcur  = tbnext;
        tbnext = t0;
    }
}

extern "C" void kernel_launch(void* const* d_in, const int* in_sizes, int n_in,
                              void* d_out, int out_size) {
    const float* f     = (const float*)d_in[0];
    const int*   nprev = (const int*)  d_in[1];
    const int*   nnext = (const int*)  d_in[2];
    const float* W     = (const float*)d_in[3];
    const float* gamma = (const float*)d_in[4];
    const float* beta  = (const float*)d_in[5];
    const float* mean  = (const float*)d_in[6];
    const float* var   = (const float*)d_in[7];
    const int n = in_sizes[0] / 32;

    cudaFuncSetAttribute(recon_kernel, cudaFuncAttributeMaxDynamicSharedMemorySize,
                         SMEM_TOTAL);
    recon_kernel<<<592, TPB, SMEM_TOTAL>>>(f, nprev, nnext, W, gamma, beta, mean, var,
                                           (float*)d_out, n);
}